// round 11
// baseline (speedup 1.0000x reference)
#include <cuda_runtime.h>
#include <cuda_fp16.h>
#include <cstdint>
#include <cstddef>

#define THREADS 768

// ---------------- smem layout (bytes) ----------------
// RING: [R:8][slot:4][gate:5][cell:16][lane:32] fp16. cell = j*2+(col&1),
// j = row within 8-row group, slot = (col>>1)&3. Gates x0.5-scaled.
#define GATE_STRIDE 1024u
#define SLOT_STRIDE 5120u
#define RG_STRIDE   20480u
#define W_OFF     163840u      // [g*32+n][72 halves] fp16 (x0.5) = 23040
#define A_OFF     186880u      // 8 gemm warps * 16 cells * 72 halves = 18432
#define BIAS_OFF  205312u      // [g:5][n:32] f32 (x0.5) = 640
#define GPROG_OFF 205952u      // 8 ints: last col done per rowgroup
#define READY_OFF 205984u      // 16 ints: rec warp progress
#define SHS_OFF   206048u      // [4][16][32] f32
#define SHH_OFF   214240u
#define SM_TOTAL  222432

// ---------------- helpers ----------------
__device__ __forceinline__ uint32_t smem_u32(const void* p) {
    uint32_t a;
    asm("{ .reg .u64 t; cvta.to.shared.u64 t, %1; cvt.u32.u64 %0, t; }"
        : "=r"(a) : "l"(p));
    return a;
}
__device__ __forceinline__ void ldsm_x4(uint32_t& r0, uint32_t& r1,
                                        uint32_t& r2, uint32_t& r3,
                                        uint32_t addr) {
    asm volatile("ldmatrix.sync.aligned.m8n8.x4.shared.b16 {%0,%1,%2,%3}, [%4];"
                 : "=r"(r0), "=r"(r1), "=r"(r2), "=r"(r3) : "r"(addr));
}
__device__ __forceinline__ void mma_f16(float* d, const uint32_t* a,
                                        uint32_t b0, uint32_t b1) {
    asm volatile(
        "mma.sync.aligned.m16n8k16.row.col.f32.f16.f16.f32 "
        "{%0,%1,%2,%3}, {%4,%5,%6,%7}, {%8,%9}, {%0,%1,%2,%3};"
        : "+f"(d[0]), "+f"(d[1]), "+f"(d[2]), "+f"(d[3])
        : "r"(a[0]), "r"(a[1]), "r"(a[2]), "r"(a[3]), "r"(b0), "r"(b1));
}
__device__ __forceinline__ uint32_t h1(float v) {
    __half h = __float2half_rn(v);
    return (uint32_t)(*reinterpret_cast<unsigned short*>(&h));
}
__device__ __forceinline__ uint32_t packh2(float a, float b) {
    __half2 h = __floats2half2_rn(a, b);
    return *reinterpret_cast<uint32_t*>(&h);
}
__device__ __forceinline__ float ldsh16(uint32_t a) {
    unsigned short v;
    asm volatile("ld.shared.u16 %0, [%1];" : "=h"(v) : "r"(a));
    float f;
    asm("cvt.f32.f16 %0, %1;" : "=f"(f) : "h"(v));
    return f;
}
__device__ __forceinline__ float tanhapx(float x) {
    float y;
    asm("tanh.approx.f32 %0, %1;" : "=f"(y) : "f"(x));
    return y;
}
__device__ __forceinline__ float sigs(float a) {   // arg pre-scaled by 0.5
    return fmaf(0.5f, tanhapx(a), 0.5f);
}

#define SPIN_GE(addr, target) do {                                          \
    int _v;                                                                 \
    do {                                                                    \
        asm volatile("ld.acquire.cta.shared.b32 %0, [%1];"                  \
                     : "=r"(_v) : "r"(addr) : "memory");                    \
    } while (_v < (target));                                                \
} while (0)
#define ST_REL(addr, val)                                                   \
    asm volatile("st.release.cta.shared.b32 [%0], %1;"                      \
                 :: "r"(addr), "r"(val) : "memory")
#define STS32(addr, val)                                                    \
    asm volatile("st.shared.b32 [%0], %1;" :: "r"(addr), "r"(val) : "memory")

struct UC {
    float uf00, uf01, uf10, uf11;
    float ui0, ui1, uo0, uo1, uc0, uc1;
};

// gates at ga + g*GATE_STRIDE (x0.5-scaled, u halved)
__device__ __forceinline__ void cell_g(uint32_t ga, const UC& u,
                                       float hup, float hl,
                                       float sup, float sl,
                                       float& s, float& h)
{
    float q0 = ldsh16(ga);
    float q1 = ldsh16(ga + GATE_STRIDE);
    float q2 = ldsh16(ga + 2 * GATE_STRIDE);
    float q3 = ldsh16(ga + 3 * GATE_STRIDE);
    float q4 = ldsh16(ga + 4 * GATE_STRIDE);
    float a0 = fmaf(u.uf01, hl, fmaf(u.uf00, hup, q0));
    float a1 = fmaf(u.uf11, hl, fmaf(u.uf10, hup, q1));
    float a2 = fmaf(u.ui1,  hl, fmaf(u.ui0,  hup, q2));
    float a3 = fmaf(u.uo1,  hl, fmaf(u.uo0,  hup, q3));
    float a4 = fmaf(u.uc1,  hl, fmaf(u.uc0,  hup, q4));
    float f0 = sigs(a0), f1 = sigs(a1);
    float ig = sigs(a2), og_ = sigs(a3), cg = sigs(a4);
    s = fmaf(f0, sup, fmaf(f1, sl, ig * cg));
    h = og_ * tanhapx(s);
}

// ================= fused persistent kernel =================
// block = (b, og). warps 0..15 rec (4 rows each); warps 16..23 GEMM,
// one per 8-row rowgroup R (rows 8R..8R+7 = rec warps 2R, 2R+1),
// producing column PAIRS (M=16 = 8 rows x 2 cols) into a 4-slot ring.
__global__ void __launch_bounds__(THREADS, 1) mdlstm_fused(
    const float* __restrict__ X,
    const float* __restrict__ wf, const float* __restrict__ uf,
    const float* __restrict__ biasf,
    const float* __restrict__ wi, const float* __restrict__ ui,
    const float* __restrict__ biasi,
    const float* __restrict__ wo, const float* __restrict__ uo,
    const float* __restrict__ biaso,
    const float* __restrict__ wc, const float* __restrict__ uc,
    const float* __restrict__ biasc,
    float* __restrict__ out)
{
    extern __shared__ __align__(16) char sm[];
    const uint32_t sbase = smem_u32(sm);
    const int tid  = threadIdx.x;
    const int lane = tid & 31;
    const int w    = tid >> 5;
    const int b    = blockIdx.x >> 2;
    const int og   = blockIdx.x & 3;

    // ---- init: W fp16 x0.5 transposed [n][k], bias f32 x0.5, flags ----
    for (int i = tid; i < 5120; i += THREADS) {
        int g  = i >> 10;
        int r  = i & 1023;
        int n  = r >> 5;
        int kp = r & 31;
        const float* W = (g == 0) ? wf : (g == 1) ? (wf + 64 * 128)
                       : (g == 2) ? wi : (g == 3) ? wo : wc;
        float w0 = 0.5f * __ldg(W + (size_t)(2 * kp) * 128 + og * 32 + n);
        float w1 = 0.5f * __ldg(W + (size_t)(2 * kp + 1) * 128 + og * 32 + n);
        uint32_t v  = h1(w0) | (h1(w1) << 16);
        STS32(sbase + W_OFF + (uint32_t)(((g * 32 + n) * 72 + 2 * kp) * 2), v);
    }
    for (int i = tid; i < 160; i += THREADS) {
        int g = i >> 5, n = i & 31;
        const float* B = (g == 0) ? biasf : (g == 1) ? (biasf + 128)
                       : (g == 2) ? biasi : (g == 3) ? biaso : biasc;
        float bv = 0.5f * __ldg(B + og * 32 + n);
        asm volatile("st.shared.f32 [%0], %1;"
                     :: "r"(sbase + BIAS_OFF + (uint32_t)(i * 4)), "f"(bv)
                     : "memory");
    }
    if (tid < 8)  *(int*)(sm + GPROG_OFF + tid * 4) = -1;
    if (tid < 16) *(int*)(sm + READY_OFF + tid * 4) = -1;
    __syncthreads();

    if (w < 16) {
        // ========================= REC role =========================
        const int R  = w >> 1;
        const int jb = (w & 1) * 4;          // row base within group
        const int o  = og * 32 + lane;

        UC u;   // halved (tanh half-angle sigmoid)
        u.uf00 = 0.5f * uf[o];        u.uf01 = 0.5f * uf[128 + o];
        u.uf10 = 0.5f * uf[256 + o];  u.uf11 = 0.5f * uf[384 + o];
        u.ui0  = 0.5f * ui[o];        u.ui1  = 0.5f * ui[128 + o];
        u.uo0  = 0.5f * uo[o];        u.uo1  = 0.5f * uo[128 + o];
        u.uc0  = 0.5f * uc[o];        u.uc1  = 0.5f * uc[128 + o];

        float* outb = out + b * 128 + o;
        float* ob0 = outb + (size_t)((4 * w + 0) * 64) * 4096;
        float* ob1 = outb + (size_t)((4 * w + 1) * 64) * 4096;
        float* ob2 = outb + (size_t)((4 * w + 2) * 64) * 4096;
        float* ob3 = outb + (size_t)((4 * w + 3) * 64) * 4096;

        const uint32_t rbase = sbase + (uint32_t)R * RG_STRIDE + (uint32_t)(lane << 1);
        const uint32_t r_prev = sbase + READY_OFF + (uint32_t)((w - 1) * 4);
        const uint32_t r_next = sbase + READY_OFF + (uint32_t)((w + 1) * 4);
        const uint32_t r_self = sbase + READY_OFF + (uint32_t)(w * 4);
        const uint32_t gpR    = sbase + GPROG_OFF + (uint32_t)(R * 4);

        float sj0 = 0.f, sj1 = 0.f, sj2 = 0.f, sj3 = 0.f;
        float hj0 = 0.f, hj1 = 0.f, hj2 = 0.f, hj3 = 0.f;

#pragma unroll 1
        for (int s = 0; s <= 66; s++) {
            if (s <= 63) SPIN_GE(gpR, s);     // gates up to col s ready

            float sup = 0.f, hup = 0.f;
            if (w > 0 && s <= 63) {
                SPIN_GE(r_prev, s + 3);
                int ps = (s + 3) & 3;
                sup = *(float*)(sm + SHS_OFF
                      + (uint32_t)(((ps * 16 + (w - 1)) * 32 + lane) * 4));
                hup = *(float*)(sm + SHH_OFF
                      + (uint32_t)(((ps * 16 + (w - 1)) * 32 + lane) * 4));
            }

            float os0 = sj0, oh0 = hj0;
            float os1 = sj1, oh1 = hj1;
            float os2 = sj2, oh2 = hj2;

            // row i consumes col s-i. cell = (jb+i)*2 + (col&1),
            // slot = (col>>1)&3
            if (s <= 63) {
                int c = s;
                uint32_t ga = rbase + (uint32_t)(((c >> 1) & 3)) * SLOT_STRIDE
                            + (uint32_t)(((jb + 0) * 2 + (c & 1)) * 64);
                float sv, hv;
                cell_g(ga, u, hup, hj0, sup, sj0, sv, hv);
                *ob0 = sv; ob0 += 4096;
                sj0 = sv; hj0 = hv;
            }
            if (s >= 1 && s <= 64) {
                int c = s - 1;
                uint32_t ga = rbase + (uint32_t)(((c >> 1) & 3)) * SLOT_STRIDE
                            + (uint32_t)(((jb + 1) * 2 + (c & 1)) * 64);
                float sv, hv;
                cell_g(ga, u, oh0, hj1, os0, sj1, sv, hv);
                *ob1 = sv; ob1 += 4096;
                sj1 = sv; hj1 = hv;
            }
            if (s >= 2 && s <= 65) {
                int c = s - 2;
                uint32_t ga = rbase + (uint32_t)(((c >> 1) & 3)) * SLOT_STRIDE
                            + (uint32_t)(((jb + 2) * 2 + (c & 1)) * 64);
                float sv, hv;
                cell_g(ga, u, oh1, hj2, os1, sj2, sv, hv);
                *ob2 = sv; ob2 += 4096;
                sj2 = sv; hj2 = hv;
            }
            if (s >= 3 && s <= 66) {
                int c = s - 3;
                uint32_t ga = rbase + (uint32_t)(((c >> 1) & 3)) * SLOT_STRIDE
                            + (uint32_t)(((jb + 3) * 2 + (c & 1)) * 64);
                float sv, hv;
                cell_g(ga, u, oh2, hj3, os2, sj3, sv, hv);
                *ob3 = sv; ob3 += 4096;
                sj3 = sv; hj3 = hv;
                if (w < 15) {
                    if (s - 7 >= 0) SPIN_GE(r_next, s - 7);
                    int slot = s & 3;
                    *(float*)(sm + SHS_OFF
                        + (uint32_t)(((slot * 16 + w) * 32 + lane) * 4)) = sv;
                    *(float*)(sm + SHH_OFF
                        + (uint32_t)(((slot * 16 + w) * 32 + lane) * 4)) = hv;
                }
            }

            __syncwarp();
            if (lane == 0) ST_REL(r_self, s);
        }
    } else {
        // ========================= GEMM role =========================
        const int R = w - 16;               // rowgroup 0..7
        const int qr = lane >> 2;
        const int qc = (lane & 3) * 2;
        const int cell = lane >> 1;         // 0..15
        const int half = lane & 1;
        const int j  = cell >> 1;           // row within group
        const int e  = cell & 1;            // col within pair

        const uint32_t astW = sbase + A_OFF + (uint32_t)(R * 2304)
                            + (uint32_t)((cell * 72 + half * 32) * 2);
        const uint32_t aB = sbase + A_OFF + (uint32_t)(R * 2304)
                          + (uint32_t)((lane & 15) * 144 + (lane >> 4) * 16);
        const uint32_t bB = sbase + W_OFF
                          + (uint32_t)((lane & 15) * 144 + (lane >> 4) * 16);
        const uint32_t rd0 = sbase + READY_OFF + (uint32_t)((2 * R) * 4);
        const uint32_t rd1 = rd0 + 4;

        const float* xrow = X + ((size_t)((8 * R + j) * 64) * 32 + b) * 64
                          + half * 32;

#pragma unroll 1
        for (int P = 0; P < 32; P++) {
            // back-pressure: slot P&3 last held pair P-4 (cols 2P-8, 2P-7);
            // consumers done with col 2P-7 once their step >= 2P-4.
            if (P >= 4) {
                SPIN_GE(rd0, 2 * P - 4);
                SPIN_GE(rd1, 2 * P - 4);
            }
            __syncwarp();

            // stage A: cell (j, e) = X row 8R+j, col 2P+e (d2 stride = 2048 f)
            {
                const float4* xp = (const float4*)(xrow + (size_t)(2 * P + e) * 2048);
#pragma unroll
                for (int q = 0; q < 8; q++) {
                    float4 v = __ldg(xp + q);
                    uint32_t p01 = packh2(v.x, v.y);
                    uint32_t p23 = packh2(v.z, v.w);
                    asm volatile("st.shared.v2.b32 [%0], {%1, %2};"
                                 :: "r"(astW + (uint32_t)(q * 8)),
                                    "r"(p01), "r"(p23) : "memory");
                }
            }
            __syncwarp();

            // A fragments (reused across 5 gates)
            uint32_t aF[4][4];
#pragma unroll
            for (int ks = 0; ks < 4; ks++)
                ldsm_x4(aF[ks][0], aF[ks][1], aF[ks][2], aF[ks][3],
                        aB + (uint32_t)(ks * 32));

            const uint32_t ringS = sbase + (uint32_t)R * RG_STRIDE
                                 + (uint32_t)(P & 3) * SLOT_STRIDE;
#pragma unroll
            for (int g = 0; g < 5; g++) {
                float acc[4][4];
#pragma unroll
                for (int ni = 0; ni < 4; ni++)
#pragma unroll
                    for (int e2 = 0; e2 < 4; e2++) acc[ni][e2] = 0.f;

#pragma unroll
                for (int ks = 0; ks < 4; ks++) {
#pragma unroll
                    for (int q = 0; q < 2; q++) {
                        uint32_t b0, b1, b2, b3;
                        ldsm_x4(b0, b1, b2, b3,
                                bB + (uint32_t)((g * 32 + q * 16) * 144 + ks * 32));
                        mma_f16(acc[2 * q],     aF[ks], b0, b2);
                        mma_f16(acc[2 * q + 1], aF[ks], b1, b3);
                    }
                }

                const uint32_t rg = ringS + (uint32_t)g * GATE_STRIDE;
#pragma unroll
                for (int ni = 0; ni < 4; ni++) {
                    int hc = ni * 8 + qc;
                    float2 bv;
                    asm("ld.shared.v2.f32 {%0, %1}, [%2];"
                        : "=f"(bv.x), "=f"(bv.y)
                        : "r"(sbase + BIAS_OFF + (uint32_t)((g * 32 + hc) * 4)));
                    uint32_t w0 = packh2(acc[ni][0] + bv.x, acc[ni][1] + bv.y);
                    uint32_t w1 = packh2(acc[ni][2] + bv.x, acc[ni][3] + bv.y);
                    uint32_t ra = rg + (uint32_t)(qr * 64 + hc * 2);
                    STS32(ra, w0);
                    STS32(ra + 512, w1);     // cells +8
                }
            }

            __syncwarp();
            if (lane == 0)
                ST_REL(sbase + GPROG_OFF + (uint32_t)(R * 4), 2 * P + 1);
        }
    }
}

// ================= launcher =================
extern "C" void kernel_launch(void* const* d_in, const int* in_sizes, int n_in,
                              void* d_out, int out_size) {
    (void)in_sizes; (void)n_in; (void)out_size;
    const float* x     = (const float*)d_in[0];
    const float* wf    = (const float*)d_in[1];
    const float* uf    = (const float*)d_in[2];
    const float* biasf = (const float*)d_in[3];
    const float* wi    = (const float*)d_in[4];
    const float* ui    = (const float*)d_in[5];
    const float* biasi = (const float*)d_in[6];
    const float* wo    = (const float*)d_in[7];
    const float* uo    = (const float*)d_in[8];
    const float* biaso = (const float*)d_in[9];
    const float* wc    = (const float*)d_in[10];
    const float* uc    = (const float*)d_in[11];
    const float* biasc = (const float*)d_in[12];
    float* out = (float*)d_out;

    cudaFuncSetAttribute(mdlstm_fused,
                         cudaFuncAttributeMaxDynamicSharedMemorySize, SM_TOTAL);
    mdlstm_fused<<<128, THREADS, SM_TOTAL>>>(
        x, wf, uf, biasf, wi, ui, biasi, wo, uo, biaso, wc, uc, biasc, out);
}